// round 14
// baseline (speedup 1.0000x reference)
#include <cuda_runtime.h>

#define NN    384
#define TS    32
#define NT    (NN / TS)      // 12
#define NBLK  (NT * NT)      // 144 < 148 SMs -> co-resident grid barrier safe
#define PA    36             // A pitch (floats), 144B: float4-aligned
#define PB    68             // dup'd B pitch (floats), 272B: float4-aligned
#define AFL   (4 * TS * PA)  // A region floats (4 groups)
#define SMEM_FLOATS (AFL + 4 * TS * PB)
#define SMEM_BYTES  (SMEM_FLOATS * 4)   // 53248 B -> dynamic smem

typedef unsigned long long ull;

// Scratch (device globals: no allocation allowed)
__device__ __align__(16) float g_u[NN * NN];
__device__ __align__(16) float g_W[NN * NN];

// Distributed grid barrier: per-block flags + one release word (monotone epochs)
__device__ unsigned g_flags[NBLK];
__device__ unsigned g_gen;

__device__ __forceinline__ void grid_barrier(unsigned epoch) {
    __syncthreads();
    if (blockIdx.x == 0) {
        int t = threadIdx.x;
        if (t >= 1 && t < NBLK) {
            while (*(volatile unsigned*)&g_flags[t] < epoch) { }
        }
        __syncthreads();
        if (t == 0) {
            __threadfence();
            *(volatile unsigned*)&g_gen = epoch;
        }
    } else {
        if (threadIdx.x == 0) {
            __threadfence();
            *(volatile unsigned*)&g_flags[blockIdx.x] = epoch;
            while (*(volatile unsigned*)&g_gen < epoch) { }
        }
    }
    __syncthreads();
    __threadfence();
}

__device__ __forceinline__ void group_barrier(int g) {
    asm volatile("bar.sync %0, 128;" :: "r"(1 + g) : "memory");
}

__device__ __forceinline__ float decode_lam(const void* p) {
    int raw = *(const int*)p;
    unsigned ub = (unsigned)raw;
    if (ub < 0x01000000u) return (float)raw;   // small-int bits (int32/int64 low)
    return __int_as_float(raw);                // float32 bits
}

// Packed fp32x2 FFMA (not emitted by ptxas from C++)
__device__ __forceinline__ void ffma2(ull& d, ull a, ull b) {
    asm("fma.rn.f32x2 %0, %1, %2, %0;" : "+l"(d) : "l"(a), "l"(b));
}
__device__ __forceinline__ float2 upk(ull v) {
    float2 f; asm("mov.b64 {%0, %1}, %2;" : "=f"(f.x), "=f"(f.y) : "l"(v)); return f;
}

extern __shared__ float smem[];
#define ASMEM(gg, k, r) smem[((gg) * TS + (k)) * PA + (r)]
#define BSMEM(gg, k, c) smem[AFL + ((gg) * TS + (k)) * PB + (c)]

// P1: u = (adj>0 && i!=j) ? exp(-lam*dist) : 0
// P2: W = od/S on S = u + offdiag(u@u)
// P3: out = u .* (W + [W | u^T] @ [u^T ; W])   (single K=768 GEMM)
// 4 warp-groups of 128 threads split K; 4x2 micro-tile; packed FFMA2 mainloop
// on pre-duplicated B. Structure identical to the 25.1us R8 kernel otherwise.
__global__ __launch_bounds__(512, 1)
void fused_kernel(const float* __restrict__ od,
                  const int*   __restrict__ adj,
                  const float* __restrict__ dist,
                  const void*  __restrict__ lam_p,
                  float*       __restrict__ out) {
    const int tid  = threadIdx.x;
    const int g    = tid >> 7;                 // group 0..3
    const int gtid = tid & 127;
    const int tyy = gtid >> 4;                 // rows 4*tyy..+3
    const int txx = gtid & 15;                 // cols 2*txx..+1
    const int lr = gtid >> 3;                  // load rows lr, lr+16
    const int lq = gtid & 7;                   // load col-quad
    const int tileX = blockIdx.x % NT;
    const int tileY = blockIdx.x / NT;
    const int rowBlk = tileY * TS;
    const int colBlk = tileX * TS;
    float* red = smem;                         // 16KB reduction scratch (reused)

    const unsigned base = *(volatile unsigned*)&g_gen;

    const int er  = tid >> 4;                  // epilogue row 0..31
    const int ec0 = 2 * (tid & 15);            // epilogue col pair
    const int esrc = (((er >> 2) << 4) + (tid & 15)) * 8 + ((er & 3) << 1);

    // ---------------- Phase 1: build u (2 elems/thread) ---------------------
    {
        const float lam = decode_lam(lam_p);
        int bidx = blockIdx.x * 1024 + tid * 2;
        int2   a2 = *(const int2*)&adj[bidx];
        float2 d2 = *(const float2*)&dist[bidx];
        int r = bidx / NN;
        int c = bidx - r * NN;
        float2 v;
        v.x = (a2.x > 0 && r != c    ) ? expf(-lam * d2.x) : 0.f;
        v.y = (a2.y > 0 && r != c + 1) ? expf(-lam * d2.y) : 0.f;
        *(float2*)&g_u[bidx] = v;
    }
    grid_barrier(base + 1);

    // ---------------- Phase 2: G = u@u, W epilogue --------------------------
    {
        ull a00 = 0, a01 = 0, a10 = 0, a11 = 0;   // (r01,c0)(r01,c1)(r23,c0)(r23,c1)
        const int tb = g * 3;                  // 3 k-tiles per group
        int p0 = tb * TS;
        float4 aR0 = *(const float4*)&g_u[(rowBlk + lr) * NN + p0 + 4 * lq];
        float4 aR1 = *(const float4*)&g_u[(rowBlk + lr + 16) * NN + p0 + 4 * lq];
        float4 bR0 = *(const float4*)&g_u[(p0 + lr) * NN + colBlk + 4 * lq];
        float4 bR1 = *(const float4*)&g_u[(p0 + lr + 16) * NN + colBlk + 4 * lq];
#pragma unroll 1
        for (int t = 0; t < 3; ++t) {
            // A transposed store
            ASMEM(g, 4 * lq + 0, lr) = aR0.x;  ASMEM(g, 4 * lq + 0, lr + 16) = aR1.x;
            ASMEM(g, 4 * lq + 1, lr) = aR0.y;  ASMEM(g, 4 * lq + 1, lr + 16) = aR1.y;
            ASMEM(g, 4 * lq + 2, lr) = aR0.z;  ASMEM(g, 4 * lq + 2, lr + 16) = aR1.z;
            ASMEM(g, 4 * lq + 3, lr) = aR0.w;  ASMEM(g, 4 * lq + 3, lr + 16) = aR1.w;
            // B natural store, duplicated pairs: col c -> positions 2c, 2c+1
            *(float4*)&BSMEM(g, lr, 8 * lq)          = make_float4(bR0.x, bR0.x, bR0.y, bR0.y);
            *(float4*)&BSMEM(g, lr, 8 * lq + 4)      = make_float4(bR0.z, bR0.z, bR0.w, bR0.w);
            *(float4*)&BSMEM(g, lr + 16, 8 * lq)     = make_float4(bR1.x, bR1.x, bR1.y, bR1.y);
            *(float4*)&BSMEM(g, lr + 16, 8 * lq + 4) = make_float4(bR1.z, bR1.z, bR1.w, bR1.w);
            group_barrier(g);
            if (t + 1 < 3) {
                int pn = (tb + t + 1) * TS;
                aR0 = *(const float4*)&g_u[(rowBlk + lr) * NN + pn + 4 * lq];
                aR1 = *(const float4*)&g_u[(rowBlk + lr + 16) * NN + pn + 4 * lq];
                bR0 = *(const float4*)&g_u[(pn + lr) * NN + colBlk + 4 * lq];
                bR1 = *(const float4*)&g_u[(pn + lr + 16) * NN + colBlk + 4 * lq];
            }
#pragma unroll
            for (int k = 0; k < TS; ++k) {
                ulonglong2 av = *(const ulonglong2*)&ASMEM(g, k, 4 * tyy);
                ulonglong2 bv = *(const ulonglong2*)&BSMEM(g, k, 4 * txx);
                ffma2(a00, av.x, bv.x);
                ffma2(a10, av.y, bv.x);
                ffma2(a01, av.x, bv.y);
                ffma2(a11, av.y, bv.y);
            }
            group_barrier(g);
        }
        __syncthreads();
        {
            float2 p00 = upk(a00), p01 = upk(a01), p10 = upk(a10), p11 = upk(a11);
            float* dst = &red[tid * 8];
            *(float4*)&dst[0] = make_float4(p00.x, p01.x, p00.y, p01.y);
            *(float4*)&dst[4] = make_float4(p10.x, p11.x, p10.y, p11.y);
        }
        __syncthreads();
        {
            float s0 = 0.f, s1 = 0.f;
#pragma unroll
            for (int gg = 0; gg < 4; ++gg) {
                float2 v = *(const float2*)&red[gg * 1024 + esrc];
                s0 += v.x; s1 += v.y;
            }
            int r = rowBlk + er;
            int c0 = colBlk + ec0;
            int idx = r * NN + c0;
            float2 uv  = *(const float2*)&g_u[idx];
            float2 odv = *(const float2*)&od[idx];
            float S0 = uv.x + ((r != c0)     ? s0 : 0.f);
            float S1 = uv.y + ((r != c0 + 1) ? s1 : 0.f);
            float2 w2;
            w2.x = (odv.x > 0.f && r != c0     && S0 > 0.f) ? (odv.x / S0) : 0.f;
            w2.y = (odv.y > 0.f && r != c0 + 1 && S1 > 0.f) ? (odv.y / S1) : 0.f;
            *(float2*)&g_W[idx] = w2;
        }
    }
    grid_barrier(base + 2);

    // ---------------- Phase 3: C = [W | u^T] @ [u^T ; W] --------------------
    // Groups 0,1: k in [0,384): A=W rows (transposed), B=u rows@colBlk (transposed)
    // Groups 2,3: k in [384,768): A=u k-rows@rowBlk (natural), B=W k-rows (natural)
    {
        ull a00 = 0, a01 = 0, a10 = 0, a11 = 0;
        const int first = (g < 2);
        float4 aR0, aR1, bR0, bR1;
        {
            int vt = g * 6;
            int p0 = first ? vt * TS : (vt - 12) * TS;
            if (first) {
                aR0 = *(const float4*)&g_W[(rowBlk + lr) * NN + p0 + 4 * lq];
                aR1 = *(const float4*)&g_W[(rowBlk + lr + 16) * NN + p0 + 4 * lq];
                bR0 = *(const float4*)&g_u[(colBlk + lr) * NN + p0 + 4 * lq];
                bR1 = *(const float4*)&g_u[(colBlk + lr + 16) * NN + p0 + 4 * lq];
            } else {
                aR0 = *(const float4*)&g_u[(p0 + lr) * NN + rowBlk + 4 * lq];
                aR1 = *(const float4*)&g_u[(p0 + lr + 16) * NN + rowBlk + 4 * lq];
                bR0 = *(const float4*)&g_W[(p0 + lr) * NN + colBlk + 4 * lq];
                bR1 = *(const float4*)&g_W[(p0 + lr + 16) * NN + colBlk + 4 * lq];
            }
        }
#pragma unroll 1
        for (int t = 0; t < 6; ++t) {
            if (first) {
                // A transposed store
                ASMEM(g, 4 * lq + 0, lr) = aR0.x;  ASMEM(g, 4 * lq + 0, lr + 16) = aR1.x;
                ASMEM(g, 4 * lq + 1, lr) = aR0.y;  ASMEM(g, 4 * lq + 1, lr + 16) = aR1.y;
                ASMEM(g, 4 * lq + 2, lr) = aR0.z;  ASMEM(g, 4 * lq + 2, lr + 16) = aR1.z;
                ASMEM(g, 4 * lq + 3, lr) = aR0.w;  ASMEM(g, 4 * lq + 3, lr + 16) = aR1.w;
                // B transposed store, duplicated: row r of gmem tile = col r here.
                // value for k=4lq+j, col lr -> BSMEM[4lq+j][2*lr, 2*lr+1]
                *(float2*)&BSMEM(g, 4 * lq + 0, 2 * lr)        = make_float2(bR0.x, bR0.x);
                *(float2*)&BSMEM(g, 4 * lq + 1, 2 * lr)        = make_float2(bR0.y, bR0.y);
                *(float2*)&BSMEM(g, 4 * lq + 2, 2 * lr)        = make_float2(bR0.z, bR0.z);
                *(float2*)&BSMEM(g, 4 * lq + 3, 2 * lr)        = make_float2(bR0.w, bR0.w);
                *(float2*)&BSMEM(g, 4 * lq + 0, 2 * (lr + 16)) = make_float2(bR1.x, bR1.x);
                *(float2*)&BSMEM(g, 4 * lq + 1, 2 * (lr + 16)) = make_float2(bR1.y, bR1.y);
                *(float2*)&BSMEM(g, 4 * lq + 2, 2 * (lr + 16)) = make_float2(bR1.z, bR1.z);
                *(float2*)&BSMEM(g, 4 * lq + 3, 2 * (lr + 16)) = make_float2(bR1.w, bR1.w);
            } else {
                // A natural store
                *(float2*)&ASMEM(g, lr, 4 * lq)          = make_float2(aR0.x, aR0.y);
                *(float2*)&ASMEM(g, lr, 4 * lq + 2)      = make_float2(aR0.z, aR0.w);
                *(float2*)&ASMEM(g, lr + 16, 4 * lq)     = make_float2(aR1.x, aR1.y);
                *(float2*)&ASMEM(g, lr + 16, 4 * lq + 2) = make_float2(aR1.z, aR1.w);
                // B natural store, duplicated pairs
                *(float4*)&BSMEM(g, lr, 8 * lq)          = make_float4(bR0.x, bR0.x, bR0.y, bR0.y);
                *(float4*)&BSMEM(g, lr, 8 * lq + 4)      = make_float4(bR0.z, bR0.z, bR0.w, bR0.w);
                *(float4*)&BSMEM(g, lr + 16, 8 * lq)     = make_float4(bR1.x, bR1.x, bR1.y, bR1.y);
                *(float4*)&BSMEM(g, lr + 16, 8 * lq + 4) = make_float4(bR1.z, bR1.z, bR1.w, bR1.w);
            }
            group_barrier(g);
            if (t + 1 < 6) {
                int vt = g * 6 + t + 1;
                int p0 = first ? vt * TS : (vt - 12) * TS;
                if (first) {
                    aR0 = *(const float4*)&g_W[(rowBlk + lr) * NN + p0 + 4 * lq];
                    aR1 = *(const float4*)&g_W[(rowBlk + lr + 16) * NN + p0 + 4 * lq];
                    bR0 = *(const float4*)&g_u[(colBlk + lr) * NN + p0 + 4 * lq];
                    bR1 = *(const float4*)&g_u[(colBlk + lr + 16) * NN + p0 + 4 * lq];
                } else {
                    aR0 = *(const float4*)&g_u[(p0 + lr) * NN + rowBlk + 4 * lq];
                    aR1 = *(const float4*)&g_u[(p0 + lr + 16) * NN + rowBlk + 4 * lq];
                    bR0 = *(const float4*)&g_W[(p0 + lr) * NN + colBlk + 4 * lq];
                    bR1 = *(const float4*)&g_W[(p0 + lr + 16) * NN + colBlk + 4 * lq];
                }
            }
#pragma unroll
            for (int k = 0; k < TS; ++k) {
                ulonglong2 av = *(const ulonglong2*)&ASMEM(g, k, 4 * tyy);
                ulonglong2 bv = *(const ulonglong2*)&BSMEM(g, k, 4 * txx);
                ffma2(a00, av.x, bv.x);
                ffma2(a10, av.y, bv.x);
                ffma2(a01, av.x, bv.y);
                ffma2(a11, av.y, bv.y);
            }
            group_barrier(g);
        }
        __syncthreads();
        {
            float2 p00 = upk(a00), p01 = upk(a01), p10 = upk(a10), p11 = upk(a11);
            float* dst = &red[tid * 8];
            *(float4*)&dst[0] = make_float4(p00.x, p01.x, p00.y, p01.y);
            *(float4*)&dst[4] = make_float4(p10.x, p11.x, p10.y, p11.y);
        }
        __syncthreads();
        {
            float s0 = 0.f, s1 = 0.f;
#pragma unroll
            for (int gg = 0; gg < 4; ++gg) {
                float2 v = *(const float2*)&red[gg * 1024 + esrc];
                s0 += v.x; s1 += v.y;
            }
            int r = rowBlk + er;
            int c0 = colBlk + ec0;
            int idx = r * NN + c0;
            float2 uv = *(const float2*)&g_u[idx];
            float2 wv = *(const float2*)&g_W[idx];
            float2 o;
            o.x = uv.x * (wv.x + s0);
            o.y = uv.y * (wv.y + s1);
            *(float2*)&out[idx] = o;
        }
    }
}

extern "C" void kernel_launch(void* const* d_in, const int* in_sizes, int n_in,
                              void* d_out, int out_size) {
    const float* od   = (const float*)d_in[0];
    const int*   adj  = (const int*)d_in[1];
    const float* dist = (const float*)d_in[2];
    const void*  lamp = d_in[3];
    float* out = (float*)d_out;

    cudaFuncSetAttribute(fused_kernel,
                         cudaFuncAttributeMaxDynamicSharedMemorySize, SMEM_BYTES);
    fused_kernel<<<NBLK, 512, SMEM_BYTES>>>(od, adj, dist, lamp, out);
}

// round 16
// speedup vs baseline: 1.3097x; 1.3097x over previous
#include <cuda_runtime.h>

#define NN    384
#define TS    32
#define NT    (NN / TS)      // 12
#define NBLK  (NT * NT)      // 144 < 148 SMs -> co-resident grid barrier safe
#define PK    388            // smem k-row pitch (floats): (4q+m)%32 distinct -> conflict-free frags
#define AHI   0
#define ALO   12416          // 32*PK
#define BHI   24832
#define BLO   37248
#define SMEM_FLOATS 49664    // 4 tiles * 32 * PK
#define SMEM_BYTES  (SMEM_FLOATS * 4)   // 198656 B < 227KB
// reuse offsets (after compute+sync): reduction + C tile + W bounce tile
#define RED0  0              // 1024 floats
#define CSM0  1024           // 32x33
#define WSM0  2112           // 32x33

// Scratch (device globals: no allocation allowed)
__device__ __align__(16) float g_u [NN * NN];
__device__ __align__(16) float g_uT[NN * NN];
__device__ __align__(16) float g_W [NN * NN];
__device__ __align__(16) float g_WT[NN * NN];

// Distributed grid barrier: per-block flags + one release word (monotone epochs)
__device__ unsigned g_flags[NBLK];
__device__ unsigned g_gen;

__device__ __forceinline__ void grid_barrier(unsigned epoch) {
    __syncthreads();
    if (blockIdx.x == 0) {
        int t = threadIdx.x;
        if (t >= 1 && t < NBLK) {
            while (*(volatile unsigned*)&g_flags[t] < epoch) { }
        }
        __syncthreads();
        if (t == 0) {
            __threadfence();
            *(volatile unsigned*)&g_gen = epoch;
        }
    } else {
        if (threadIdx.x == 0) {
            __threadfence();
            *(volatile unsigned*)&g_flags[blockIdx.x] = epoch;
            while (*(volatile unsigned*)&g_gen < epoch) { }
        }
    }
    __syncthreads();
    __threadfence();
}

__device__ __forceinline__ float decode_lam(const void* p) {
    int raw = *(const int*)p;
    unsigned ub = (unsigned)raw;
    if (ub < 0x01000000u) return (float)raw;   // small-int bits (int32/int64 low)
    return __int_as_float(raw);                // float32 bits
}

__device__ __forceinline__ float tf32r(float x) {
    unsigned u; asm("cvt.rna.tf32.f32 %0, %1;" : "=r"(u) : "f"(x));
    return __uint_as_float(u);
}

__device__ __forceinline__ void mma_tf32(float& d0, float& d1, float& d2, float& d3,
                                         unsigned a0, unsigned a1, unsigned a2, unsigned a3,
                                         unsigned b0, unsigned b1) {
    asm("mma.sync.aligned.m16n8k8.row.col.f32.tf32.tf32.f32 "
        "{%0,%1,%2,%3},{%4,%5,%6,%7},{%8,%9},{%0,%1,%2,%3};"
        : "+f"(d0), "+f"(d1), "+f"(d2), "+f"(d3)
        : "r"(a0), "r"(a1), "r"(a2), "r"(a3), "r"(b0), "r"(b1));
}

extern __shared__ float smem[];

// Stage A rows (aRow0..+32) and B rows (bRow0..+32), K=384 cols, into hi/lo tiles.
// Coalesced LDG.128, STS.128; hi = tf32(x), lo = tf32(x - hi).
__device__ __forceinline__ void stage(const float* __restrict__ srcA, int aRow0,
                                      const float* __restrict__ srcB, int bRow0,
                                      int tid) {
#pragma unroll
    for (int it = 0; it < 6; ++it) {
        int qq = it * 512 + tid;
        int r  = qq / 96;            // 0..31
        int cq = qq - r * 96;        // col-quad 0..95
        float4 va = *(const float4*)&srcA[(aRow0 + r) * NN + 4 * cq];
        float4 vb = *(const float4*)&srcB[(bRow0 + r) * NN + 4 * cq];
        float4 vah = make_float4(tf32r(va.x), tf32r(va.y), tf32r(va.z), tf32r(va.w));
        float4 val = make_float4(tf32r(va.x - vah.x), tf32r(va.y - vah.y),
                                 tf32r(va.z - vah.z), tf32r(va.w - vah.w));
        float4 vbh = make_float4(tf32r(vb.x), tf32r(vb.y), tf32r(vb.z), tf32r(vb.w));
        float4 vbl = make_float4(tf32r(vb.x - vbh.x), tf32r(vb.y - vbh.y),
                                 tf32r(vb.z - vbh.z), tf32r(vb.w - vbh.w));
        int off = r * PK + 4 * cq;
        *(float4*)&smem[AHI + off] = vah;
        *(float4*)&smem[ALO + off] = val;
        *(float4*)&smem[BHI + off] = vbh;
        *(float4*)&smem[BLO + off] = vbl;
    }
}

// One K-half pass: 24 k8-steps of 3xTF32 mma for this warp's m16n8 tile.
__device__ __forceinline__ void pass_compute(int m0, int n0, int kb, int q, int m,
                                             float accM[4], float accC[4]) {
    const unsigned* sa_hi = (const unsigned*)&smem[AHI + (m0 + q) * PK + m];
    const unsigned* sa_lo = (const unsigned*)&smem[ALO + (m0 + q) * PK + m];
    const unsigned* sb_hi = (const unsigned*)&smem[BHI + (n0 + q) * PK + m];
    const unsigned* sb_lo = (const unsigned*)&smem[BLO + (n0 + q) * PK + m];
#pragma unroll
    for (int s = 0; s < 24; ++s) {
        int k0 = kb + 8 * s;
        unsigned a0h = sa_hi[k0],          a1h = sa_hi[k0 + 8 * PK];
        unsigned a2h = sa_hi[k0 + 4],      a3h = sa_hi[k0 + 8 * PK + 4];
        unsigned a0l = sa_lo[k0],          a1l = sa_lo[k0 + 8 * PK];
        unsigned a2l = sa_lo[k0 + 4],      a3l = sa_lo[k0 + 8 * PK + 4];
        unsigned b0h = sb_hi[k0],          b1h = sb_hi[k0 + 4];
        unsigned b0l = sb_lo[k0],          b1l = sb_lo[k0 + 4];
        mma_tf32(accM[0], accM[1], accM[2], accM[3], a0h, a1h, a2h, a3h, b0h, b1h);
        mma_tf32(accC[0], accC[1], accC[2], accC[3], a0h, a1h, a2h, a3h, b0l, b1l);
        mma_tf32(accC[0], accC[1], accC[2], accC[3], a0l, a1l, a2l, a3l, b0h, b1h);
    }
}

// Reduce 2 K-half partials (warp w and w+8 share tile w&7) and write C tile to smem.
__device__ __forceinline__ void reduce_to_csm(int w, int lane, int q, int m,
                                              int m0, int n0,
                                              float accM[4], float accC[4]) {
    __syncthreads();                     // all compute done; smem reusable
    float c0 = accM[0] + accC[0], c1 = accM[1] + accC[1];
    float c2 = accM[2] + accC[2], c3 = accM[3] + accC[3];
    if (w >= 8)
        *(float4*)&smem[RED0 + (w - 8) * 128 + lane * 4] = make_float4(c0, c1, c2, c3);
    __syncthreads();
    if (w < 8) {
        float4 p = *(const float4*)&smem[RED0 + w * 128 + lane * 4];
        c0 += p.x; c1 += p.y; c2 += p.z; c3 += p.w;
        smem[CSM0 + (m0 + q) * 33 + n0 + 2 * m]         = c0;
        smem[CSM0 + (m0 + q) * 33 + n0 + 2 * m + 1]     = c1;
        smem[CSM0 + (m0 + q + 8) * 33 + n0 + 2 * m]     = c2;
        smem[CSM0 + (m0 + q + 8) * 33 + n0 + 2 * m + 1] = c3;
    }
    __syncthreads();
}

// P1: u = (adj>0 && i!=j) ? exp(-lam*dist) : 0   (+ u^T)
// P2: W = od/S on S = u + offdiag(u@u)           (+ W^T)
// P3: out = u .* (W + [W | u^T] @ [u^T ; W])     (two full-K tensor passes)
__global__ __launch_bounds__(512, 1)
void fused_kernel(const float* __restrict__ od,
                  const int*   __restrict__ adj,
                  const float* __restrict__ dist,
                  const void*  __restrict__ lam_p,
                  float*       __restrict__ out) {
    const int tid  = threadIdx.x;
    const int w    = tid >> 5;
    const int lane = tid & 31;
    const int q    = lane >> 2;            // fragment row group 0..7
    const int m    = lane & 3;             // fragment col group 0..3
    const int tileid = w & 7;
    const int m0 = 16 * (tileid >> 2);
    const int n0 = 8  * (tileid & 3);
    const int kb = 192 * (w >> 3);         // K-half base
    const int tileX = blockIdx.x % NT;
    const int tileY = blockIdx.x / NT;
    const int rowBlk = tileY * TS;
    const int colBlk = tileX * TS;

    const unsigned base = *(volatile unsigned*)&g_gen;

    const int er  = tid >> 4;              // epilogue row 0..31
    const int ec0 = 2 * (tid & 15);        // epilogue col pair
    const int cj  = tid >> 4;              // transpose-read col
    const int ri  = tid & 15;              // transpose-read row pair

    // ---------------- Phase 1: build u and u^T ------------------------------
    {
        const float lam = decode_lam(lam_p);
        int rr = rowBlk + er;
        int cc = colBlk + ec0;
        int idx = rr * NN + cc;
        int2   a2 = *(const int2*)&adj[idx];
        float2 d2 = *(const float2*)&dist[idx];
        float2 v;
        v.x = (a2.x > 0 && rr != cc    ) ? expf(-lam * d2.x) : 0.f;
        v.y = (a2.y > 0 && rr != cc + 1) ? expf(-lam * d2.y) : 0.f;
        *(float2*)&g_u[idx] = v;
        smem[CSM0 + er * 33 + ec0]     = v.x;
        smem[CSM0 + er * 33 + ec0 + 1] = v.y;
        __syncthreads();
        float t0 = smem[CSM0 + (2 * ri)     * 33 + cj];
        float t1 = smem[CSM0 + (2 * ri + 1) * 33 + cj];
        *(float2*)&g_uT[(colBlk + cj) * NN + rowBlk + 2 * ri] = make_float2(t0, t1);
        __syncthreads();
    }
    grid_barrier(base + 1);

    // ---------------- Phase 2: G = u@u -> W, W^T ----------------------------
    {
        float accM[4] = {0.f, 0.f, 0.f, 0.f};
        float accC[4] = {0.f, 0.f, 0.f, 0.f};
        // A[mrow][k] = u[rowBlk+mrow][k];  Bsm[n][k] = u[k][colBlk+n] = uT[colBlk+n][k]
        stage(g_u, rowBlk, g_uT, colBlk, tid);
        __syncthreads();
        pass_compute(m0, n0, kb, q, m, accM, accC);
        reduce_to_csm(w, lane, q, m, m0, n0, accM, accC);
        // epilogue: W = od/S, write g_W natural + g_WT via bounce
        {
            int r  = rowBlk + er;
            int c0 = colBlk + ec0;
            int idx = r * NN + c0;
            float G0 = smem[CSM0 + er * 33 + ec0];
            float G1 = smem[CSM0 + er * 33 + ec0 + 1];
            float2 uv  = *(const float2*)&g_u[idx];
            float2 odv = *(const float2*)&od[idx];
            float S0 = uv.x + ((r != c0)     ? G0 : 0.f);
            float S1 = uv.y + ((r != c0 + 1) ? G1 : 0.f);
            float W0 = (odv.x > 0.f && r != c0     && S0 > 0.f) ? (odv.x / S0) : 0.f;
            float W1 = (odv.y > 0.f && r != c0 + 1 && S1 > 0.f) ? (odv.y / S1) : 0.f;
            *(float2*)&g_W[idx] = make_float2(W0, W1);
            smem[WSM0 + er * 33 + ec0]     = W0;
            smem[WSM0 + er * 33 + ec0 + 1] = W1;
        }
        __syncthreads();
        {
            float t0 = smem[WSM0 + (2 * ri)     * 33 + cj];
            float t1 = smem[WSM0 + (2 * ri + 1) * 33 + cj];
            *(float2*)&g_WT[(colBlk + cj) * NN + rowBlk + 2 * ri] = make_float2(t0, t1);
        }
    }
    grid_barrier(base + 2);

    // ---------------- Phase 3: C = W@u^T + u^T@W  (two full-K passes) -------
    {
        float accM[4] = {0.f, 0.f, 0.f, 0.f};
        float accC[4] = {0.f, 0.f, 0.f, 0.f};
        // pass 1: A = W rows; Bsm[n][k] = uT[k][colBlk+n] = u[colBlk+n][k]
        stage(g_W, rowBlk, g_u, colBlk, tid);
        __syncthreads();
        pass_compute(m0, n0, kb, q, m, accM, accC);
        __syncthreads();
        // pass 2: A[mrow][k] = uT[rowBlk+mrow][k]; Bsm[n][k] = W[k][colBlk+n] = WT[colBlk+n][k]
        stage(g_uT, rowBlk, g_WT, colBlk, tid);
        __syncthreads();
        pass_compute(m0, n0, kb, q, m, accM, accC);
        reduce_to_csm(w, lane, q, m, m0, n0, accM, accC);
        // epilogue: out = u .* (W + C)
        {
            int r  = rowBlk + er;
            int c0 = colBlk + ec0;
            int idx = r * NN + c0;
            float C0 = smem[CSM0 + er * 33 + ec0];
            float C1 = smem[CSM0 + er * 33 + ec0 + 1];
            float2 uv = *(const float2*)&g_u[idx];
            float2 wv = *(const float2*)&g_W[idx];
            float2 o;
            o.x = uv.x * (wv.x + C0);
            o.y = uv.y * (wv.y + C1);
            *(float2*)&out[idx] = o;
        }
    }
}

extern "C" void kernel_launch(void* const* d_in, const int* in_sizes, int n_in,
                              void* d_out, int out_size) {
    const float* od   = (const float*)d_in[0];
    const int*   adj  = (const int*)d_in[1];
    const float* dist = (const float*)d_in[2];
    const void*  lamp = d_in[3];
    float* out = (float*)d_out;

    cudaFuncSetAttribute(fused_kernel,
                         cudaFuncAttributeMaxDynamicSharedMemorySize, SMEM_BYTES);
    fused_kernel<<<NBLK, 512, SMEM_BYTES>>>(od, adj, dist, lamp, out);
}